// round 17
// baseline (speedup 1.0000x reference)
#include <cuda_runtime.h>
#include <cuda_fp16.h>
#include <mma.h>

using namespace nvcuda;

#define NN 100000
#define EE 1600000
#define F  128
#define GEMM_BLOCKS 782
#define HIST_BLOCKS 1563   // 1024 edges per block (256 thr x 4)

// ---------------- device scratch (no allocations allowed) ----------------
__device__ __align__(16) __half g_bufH[(size_t)NN * F];   // 25.6 MB (gather buffer, fp16)
__device__ __align__(16) __half g_bufB16[(size_t)NN * F]; // 25.6 MB (layer output h, fp16)
__device__ float g_dinv[NN];
__device__ int   g_cnt[NN];
__device__ int   g_rowptr[NN + 1];
__device__ int   g_cursor[NN];
__device__ int   g_col[EE];
__device__ int   g_is64;

// read edge index element (handles int32 or int64 storage)
__device__ __forceinline__ int ld_idx(const void* ei, size_t pos) {
    if (g_is64) return (int)((const long long*)ei)[pos];
    return ((const int*)ei)[pos];
}

// ---------------- zero + dtype detect (fused) ----------------
__global__ void k_zero_detect(const int* __restrict__ ei32) {
    int i = blockIdx.x * blockDim.x + threadIdx.x;
    if (i < NN) g_cnt[i] = 0;
    if (blockIdx.x == 0) {
        __shared__ int nz;
        if (threadIdx.x == 0) nz = 0;
        __syncthreads();
        // int64 values < 2^31 -> every odd 32-bit word is 0; int32 -> ~never.
        if (ei32[2 * threadIdx.x + 1] != 0) atomicOr(&nz, 1);
        __syncthreads();
        if (threadIdx.x == 0) g_is64 = (nz == 0) ? 1 : 0;
    }
}

// ---------------- FAT kernel: gemm1 (raw XW, no dinv) + edge histogram ----------------
// blocks [0, GEMM_BLOCKS): g_bufH[row] = fp16( x[row] @ W1 )   (fp16 HMMA, fp32 acc)
// blocks [GEMM_BLOCKS, +HIST_BLOCKS): histogram of dst into g_cnt
__global__ void k_gemm1_hist(const float* __restrict__ x, const float* __restrict__ W,
                             const void* __restrict__ ei) {
    __shared__ float smem[8192];   // 32 KB; gemm blocks only
    int tid = threadIdx.x;

    if (blockIdx.x >= GEMM_BLOCKS) {
        int b = blockIdx.x - GEMM_BLOCKS;
#pragma unroll
        for (int u = 0; u < 4; u++) {
            int e = b * 1024 + u * 256 + tid;
            if (e < EE) {
                int d = ld_idx(ei, (size_t)EE + e);
                atomicAdd(&g_cnt[d], 1);
            }
        }
        return;
    }

    __half* sA = reinterpret_cast<__half*>(smem);        // 128 x 40 halfs
    __half* sB = reinterpret_cast<__half*>(smem + 2560); // 32 x 136 halfs
    int warp = tid >> 5, lane = tid & 31;
    int wr = warp >> 1, wc = warp & 1;
    int rowBase = blockIdx.x * 128;

    wmma::fragment<wmma::accumulator, 16, 16, 16, float> acc[2][4];
#pragma unroll
    for (int mt = 0; mt < 2; mt++)
#pragma unroll
        for (int nt = 0; nt < 4; nt++) wmma::fill_fragment(acc[mt][nt], 0.0f);

    for (int kc = 0; kc < 4; kc++) {
        __syncthreads();
#pragma unroll
        for (int i = 0; i < 8; i++) {
            int idx = tid + 256 * i;
            int r = idx >> 4, c2 = idx & 15;
            int row = rowBase + r;
            float2 v = make_float2(0.f, 0.f);
            if (row < NN) v = ((const float2*)x)[(size_t)row * 64 + kc * 16 + c2];
            *(__half2*)&sA[r * 40 + c2 * 2] = __floats2half2_rn(v.x, v.y);
        }
#pragma unroll
        for (int i = 0; i < 8; i++) {
            int idx = tid + 256 * i;
            int k = idx >> 6, c2 = idx & 63;
            float2 v = ((const float2*)W)[(size_t)(kc * 32 + k) * 64 + c2];
            *(__half2*)&sB[k * 136 + c2 * 2] = __floats2half2_rn(v.x, v.y);
        }
        __syncthreads();

#pragma unroll
        for (int k16 = 0; k16 < 2; k16++) {
            wmma::fragment<wmma::matrix_a, 16, 16, 16, __half, wmma::row_major> a[2];
#pragma unroll
            for (int mt = 0; mt < 2; mt++)
                wmma::load_matrix_sync(a[mt], sA + (wr * 32 + mt * 16) * 40 + k16 * 16, 40);
#pragma unroll
            for (int nt = 0; nt < 4; nt++) {
                wmma::fragment<wmma::matrix_b, 16, 16, 16, __half, wmma::row_major> b;
                wmma::load_matrix_sync(b, sB + (k16 * 16) * 136 + wc * 64 + nt * 16, 136);
#pragma unroll
                for (int mt = 0; mt < 2; mt++)
                    wmma::mma_sync(acc[mt][nt], a[mt], b, acc[mt][nt]);
            }
        }
    }

    __syncthreads();
    float* stage = smem + warp * 1024;
#pragma unroll
    for (int mt = 0; mt < 2; mt++) {
#pragma unroll
        for (int nt = 0; nt < 4; nt++)
            wmma::store_matrix_sync(stage + nt * 16, acc[mt][nt], 64, wmma::mem_row_major);
        __syncwarp();
#pragma unroll
        for (int i = 0; i < 8; i++) {
            int idx = lane + 32 * i;
            int r = idx >> 4, c4 = idx & 15;
            int row = rowBase + wr * 32 + mt * 16 + r;
            if (row < NN) {
                float4 v = *(float4*)&stage[r * 64 + c4 * 4];
                __half2 h01 = __floats2half2_rn(v.x, v.y);    // raw XW, no dinv
                __half2 h23 = __floats2half2_rn(v.z, v.w);
                uint2 u;
                u.x = *(unsigned*)&h01;
                u.y = *(unsigned*)&h23;
                ((uint2*)g_bufH)[(size_t)row * 32 + (wc * 16 + c4)] = u;
            }
        }
        __syncwarp();
    }
}

// ---------------- fused scan (single block, 1024 threads): rowptr/cursor/dinv ----------------
__global__ void k_scan_fused() {
    __shared__ int s[1024];
    const int CH = (NN + 1023) / 1024;   // 98
    int t = threadIdx.x;
    int base = t * CH;
    int loc = 0;
    for (int i = 0; i < CH; i++) {
        int idx = base + i;
        if (idx < NN) {
            int c = g_cnt[idx];
            g_dinv[idx] = rsqrtf((float)(c + 1));
            loc += c;
        }
    }
    s[t] = loc;
    __syncthreads();
    for (int off = 1; off < 1024; off <<= 1) {
        int add = (t >= off) ? s[t - off] : 0;
        __syncthreads();
        s[t] += add;
        __syncthreads();
    }
    int run = s[t] - loc;    // exclusive prefix for this thread's chunk
    for (int i = 0; i < CH; i++) {
        int idx = base + i;
        if (idx < NN) {
            g_rowptr[idx] = run;
            g_cursor[idx] = run;
            run += g_cnt[idx];
        }
    }
    if (t == 0) g_rowptr[NN] = EE;
}

__global__ void k_fill(const void* __restrict__ ei) {
    int e = blockIdx.x * blockDim.x + threadIdx.x;
    if (e < EE) {
        int d = ld_idx(ei, (size_t)EE + e);
        int s = ld_idx(ei, (size_t)e);
        int p = atomicAdd(&g_cursor[d], 1);
        g_col[p] = s;
    }
}

// ---------------- GEMM layers 2/3 (fp16 wmma, dinv in epilogue) ----------------
__global__ void k_gemm(const float* __restrict__ W) {
    __shared__ float smem[8192];
    __half* sA = reinterpret_cast<__half*>(smem);
    __half* sB = reinterpret_cast<__half*>(smem + 2560);

    int tid  = threadIdx.x;
    int warp = tid >> 5, lane = tid & 31;
    int wr = warp >> 1, wc = warp & 1;
    int rowBase = blockIdx.x * 128;

    wmma::fragment<wmma::accumulator, 16, 16, 16, float> acc[2][4];
#pragma unroll
    for (int mt = 0; mt < 2; mt++)
#pragma unroll
        for (int nt = 0; nt < 4; nt++) wmma::fill_fragment(acc[mt][nt], 0.0f);

    for (int kc = 0; kc < 4; kc++) {
        __syncthreads();
#pragma unroll
        for (int i = 0; i < 8; i++) {
            int idx = tid + 256 * i;
            int r = idx >> 4, c2 = idx & 15;
            int row = rowBase + r;
            unsigned u = 0;
            if (row < NN) u = ((const unsigned*)g_bufB16)[(size_t)row * 64 + kc * 16 + c2];
            *(unsigned*)&sA[r * 40 + c2 * 2] = u;
        }
#pragma unroll
        for (int i = 0; i < 8; i++) {
            int idx = tid + 256 * i;
            int k = idx >> 6, c2 = idx & 63;
            float2 v = ((const float2*)W)[(size_t)(kc * 32 + k) * 64 + c2];
            *(__half2*)&sB[k * 136 + c2 * 2] = __floats2half2_rn(v.x, v.y);
        }
        __syncthreads();

#pragma unroll
        for (int k16 = 0; k16 < 2; k16++) {
            wmma::fragment<wmma::matrix_a, 16, 16, 16, __half, wmma::row_major> a[2];
#pragma unroll
            for (int mt = 0; mt < 2; mt++)
                wmma::load_matrix_sync(a[mt], sA + (wr * 32 + mt * 16) * 40 + k16 * 16, 40);
#pragma unroll
            for (int nt = 0; nt < 4; nt++) {
                wmma::fragment<wmma::matrix_b, 16, 16, 16, __half, wmma::row_major> b;
                wmma::load_matrix_sync(b, sB + (k16 * 16) * 136 + wc * 64 + nt * 16, 136);
#pragma unroll
                for (int mt = 0; mt < 2; mt++)
                    wmma::mma_sync(acc[mt][nt], a[mt], b, acc[mt][nt]);
            }
        }
    }

    __syncthreads();
    float* stage = smem + warp * 1024;
#pragma unroll
    for (int mt = 0; mt < 2; mt++) {
#pragma unroll
        for (int nt = 0; nt < 4; nt++)
            wmma::store_matrix_sync(stage + nt * 16, acc[mt][nt], 64, wmma::mem_row_major);
        __syncwarp();
#pragma unroll
        for (int i = 0; i < 8; i++) {
            int idx = lane + 32 * i;
            int r = idx >> 4, c4 = idx & 15;
            int row = rowBase + wr * 32 + mt * 16 + r;
            if (row < NN) {
                float s = g_dinv[row];
                float4 v = *(float4*)&stage[r * 64 + c4 * 4];
                __half2 h01 = __floats2half2_rn(v.x * s, v.y * s);
                __half2 h23 = __floats2half2_rn(v.z * s, v.w * s);
                uint2 u;
                u.x = *(unsigned*)&h01;
                u.y = *(unsigned*)&h23;
                ((uint2*)g_bufH)[(size_t)row * 32 + (wc * 16 + c4)] = u;
            }
        }
        __syncwarp();
    }
}

// ---------------- aggregation layer 1: bufH holds raw XW; apply dinv per row here ----------------
// out_i = relu( dinv_i * ( dinv_i*v_i + sum_j dinv_j*v_j ) + b )
__global__ void k_agg1(const float* __restrict__ bias) {
    int w = (blockIdx.x * blockDim.x + threadIdx.x) >> 5;
    int lane = threadIdx.x & 31;
    if (w >= NN) return;
    const uint2* g2 = (const uint2*)g_bufH;
    float di = g_dinv[w];
    float4 acc;
    {
        uint2 u = g2[(size_t)w * 32 + lane];
        float2 f01 = __half22float2(*(__half2*)&u.x);
        float2 f23 = __half22float2(*(__half2*)&u.y);
        acc = make_float4(di * f01.x, di * f01.y, di * f23.x, di * f23.y);
    }
    int s = g_rowptr[w], e = g_rowptr[w + 1];
    for (int p = s; p < e; p++) {
        int j = g_col[p];
        float dj = g_dinv[j];                    // warp-uniform -> broadcast
        uint2 u = g2[(size_t)j * 32 + lane];
        float2 f01 = __half22float2(*(__half2*)&u.x);
        float2 f23 = __half22float2(*(__half2*)&u.y);
        acc.x = fmaf(dj, f01.x, acc.x);
        acc.y = fmaf(dj, f01.y, acc.y);
        acc.z = fmaf(dj, f23.x, acc.z);
        acc.w = fmaf(dj, f23.y, acc.w);
    }
    float4 b = ((const float4*)bias)[lane];
    __half2 h01 = __floats2half2_rn(fmaxf(fmaf(acc.x, di, b.x), 0.f),
                                    fmaxf(fmaf(acc.y, di, b.y), 0.f));
    __half2 h23 = __floats2half2_rn(fmaxf(fmaf(acc.z, di, b.z), 0.f),
                                    fmaxf(fmaf(acc.w, di, b.w), 0.f));
    uint2 u;
    u.x = *(unsigned*)&h01;
    u.y = *(unsigned*)&h23;
    ((uint2*)g_bufB16)[(size_t)w * 32 + lane] = u;
}

// ---------------- aggregation layers 2/3 (bufH already dinv-scaled) ----------------
__global__ void k_agg(const float* __restrict__ bias) {
    int w = (blockIdx.x * blockDim.x + threadIdx.x) >> 5;
    int lane = threadIdx.x & 31;
    if (w >= NN) return;
    const uint2* g2 = (const uint2*)g_bufH;
    float4 acc;
    {
        uint2 u = g2[(size_t)w * 32 + lane];
        float2 f01 = __half22float2(*(__half2*)&u.x);
        float2 f23 = __half22float2(*(__half2*)&u.y);
        acc = make_float4(f01.x, f01.y, f23.x, f23.y);
    }
    int s = g_rowptr[w], e = g_rowptr[w + 1];
    for (int p = s; p < e; p++) {
        int j = g_col[p];
        uint2 u = g2[(size_t)j * 32 + lane];
        float2 f01 = __half22float2(*(__half2*)&u.x);
        float2 f23 = __half22float2(*(__half2*)&u.y);
        acc.x += f01.x; acc.y += f01.y; acc.z += f23.x; acc.w += f23.y;
    }
    float di = g_dinv[w];
    float4 b = ((const float4*)bias)[lane];
    __half2 h01 = __floats2half2_rn(fmaxf(fmaf(acc.x, di, b.x), 0.f),
                                    fmaxf(fmaf(acc.y, di, b.y), 0.f));
    __half2 h23 = __floats2half2_rn(fmaxf(fmaf(acc.z, di, b.z), 0.f),
                                    fmaxf(fmaf(acc.w, di, b.w), 0.f));
    uint2 u;
    u.x = *(unsigned*)&h01;
    u.y = *(unsigned*)&h23;
    ((uint2*)g_bufB16)[(size_t)w * 32 + lane] = u;
}

// ---------------- fused heads (fp16 wmma first layer, fp32 second layer) ----------------
__global__ void k_head(const float* __restrict__ Wp1, const float* __restrict__ bp1,
                       const float* __restrict__ Wp2, const float* __restrict__ bp2,
                       const float* __restrict__ Wt1, const float* __restrict__ bt1,
                       const float* __restrict__ Wt2, const float* __restrict__ bt2,
                       float* __restrict__ out) {
    __shared__ __align__(16) char smemraw[49152];      // 48 KB
    __half* sA = (__half*)smemraw;                     // 128 x 40 halfs
    __half* sB = (__half*)(smemraw + 10240);           // 32 x 200 halfs (192 used)
    float*  stageF = (float*)smemraw;                  // epilogue: 4 x 16x192 fp32

    int tid  = threadIdx.x;
    int warp = tid >> 5, lane = tid & 31;
    int rowBase = blockIdx.x * 128;

    wmma::fragment<wmma::accumulator, 16, 16, 16, float> acc[12];
#pragma unroll
    for (int nt = 0; nt < 12; nt++) wmma::fill_fragment(acc[nt], 0.0f);

    for (int kc = 0; kc < 4; kc++) {
        __syncthreads();
#pragma unroll
        for (int i = 0; i < 8; i++) {
            int idx = tid + 256 * i;
            int r = idx >> 4, c2 = idx & 15;
            int row = rowBase + r;
            unsigned u = 0;
            if (row < NN) u = ((const unsigned*)g_bufB16)[(size_t)row * 64 + kc * 16 + c2];
            *(unsigned*)&sA[r * 40 + c2 * 2] = u;
        }
#pragma unroll
        for (int i = 0; i < 12; i++) {
            int idx = tid + 256 * i;
            int k = idx / 96, c2 = idx % 96;
            int kg = kc * 32 + k;
            float2 v;
            if (c2 < 64) v = ((const float2*)Wp1)[(size_t)kg * 64 + c2];
            else         v = ((const float2*)Wt1)[(size_t)kg * 32 + (c2 - 64)];
            *(__half2*)&sB[k * 200 + c2 * 2] = __floats2half2_rn(v.x, v.y);
        }
        __syncthreads();

#pragma unroll
        for (int k16 = 0; k16 < 2; k16++) {
            wmma::fragment<wmma::matrix_a, 16, 16, 16, __half, wmma::row_major> a;
            wmma::load_matrix_sync(a, sA + (warp * 16) * 40 + k16 * 16, 40);
#pragma unroll
            for (int nt = 0; nt < 12; nt++) {
                wmma::fragment<wmma::matrix_b, 16, 16, 16, __half, wmma::row_major> b;
                wmma::load_matrix_sync(b, sB + (k16 * 16) * 200 + nt * 16, 200);
                wmma::mma_sync(acc[nt], a, b, acc[nt]);
            }
        }
    }

    float4 bP = ((const float4*)bp1)[lane];
    float2 bT = ((const float2*)bt1)[lane];
    float wp2a[4], wp2b[4];
#pragma unroll
    for (int i = 0; i < 4; i++) {
        wp2a[i] = Wp2[(lane * 4 + i) * 2];
        wp2b[i] = Wp2[(lane * 4 + i) * 2 + 1];
    }
    float wt2_0 = Wt2[lane * 2], wt2_1 = Wt2[lane * 2 + 1];
    float bpos0 = bp2[0], bpos1 = bp2[1], btime = bt2[0];

    __syncthreads();
    for (int batch = 0; batch < 2; batch++) {
        bool mine = (warp >> 2) == batch;
        if (mine) {
            float* st = stageF + (warp & 3) * 3072;   // 16 x 192
#pragma unroll
            for (int nt = 0; nt < 12; nt++)
                wmma::store_matrix_sync(st + nt * 16, acc[nt], 192, wmma::mem_row_major);
            __syncwarp();
#pragma unroll 2
            for (int r = 0; r < 16; r++) {
                int row = rowBase + warp * 16 + r;
                float4 hv = *(float4*)&st[r * 192 + lane * 4];
                float2 tvv = *(float2*)&st[r * 192 + 128 + lane * 2];
                float p0 = fmaxf(hv.x + bP.x, 0.f);
                float p1 = fmaxf(hv.y + bP.y, 0.f);
                float p2 = fmaxf(hv.z + bP.z, 0.f);
                float p3 = fmaxf(hv.w + bP.w, 0.f);
                float t0 = fmaxf(tvv.x + bT.x, 0.f);
                float t1 = fmaxf(tvv.y + bT.y, 0.f);
                float px = p0 * wp2a[0] + p1 * wp2a[1] + p2 * wp2a[2] + p3 * wp2a[3];
                float py = p0 * wp2b[0] + p1 * wp2b[1] + p2 * wp2b[2] + p3 * wp2b[3];
                float tv = t0 * wt2_0 + t1 * wt2_1;
#pragma unroll
                for (int off = 16; off; off >>= 1) {
                    px += __shfl_down_sync(0xffffffffu, px, off);
                    py += __shfl_down_sync(0xffffffffu, py, off);
                    tv += __shfl_down_sync(0xffffffffu, tv, off);
                }
                if (lane == 0 && row < NN) {
                    out[(size_t)row * 3 + 0] = px + bpos0;
                    out[(size_t)row * 3 + 1] = py + bpos1;
                    out[(size_t)row * 3 + 2] = tv + btime;
                }
            }
        }
        __syncthreads();
    }
}

// ---------------- launch ----------------
extern "C" void kernel_launch(void* const* d_in, const int* in_sizes, int n_in,
                              void* d_out, int out_size) {
    const float* x   = (const float*)d_in[0];
    const void*  ei  = d_in[1];
    const float* W1  = (const float*)d_in[2];  const float* b1  = (const float*)d_in[3];
    const float* W2  = (const float*)d_in[4];  const float* b2  = (const float*)d_in[5];
    const float* W3  = (const float*)d_in[6];  const float* b3  = (const float*)d_in[7];
    const float* Wp1 = (const float*)d_in[8];  const float* bp1 = (const float*)d_in[9];
    const float* Wp2 = (const float*)d_in[10]; const float* bp2 = (const float*)d_in[11];
    const float* Wt1 = (const float*)d_in[12]; const float* bt1 = (const float*)d_in[13];
    const float* Wt2 = (const float*)d_in[14]; const float* bt2 = (const float*)d_in[15];
    float* out = (float*)d_out;

    int nb256 = (NN + 255) / 256;
    int ebl   = (EE + 255) / 256;
    int gemmGrid = (NN + 127) / 128;   // 782
    int aggGrid  = (NN + 7) / 8;       // 1 warp per node
    int headGrid = (NN + 127) / 128;

    k_zero_detect<<<nb256, 256>>>((const int*)ei);
    k_gemm1_hist<<<GEMM_BLOCKS + HIST_BLOCKS, 256>>>(x, W1, ei);   // gemm1 + hist overlapped
    k_scan_fused<<<1, 1024>>>();
    k_fill<<<ebl, 256>>>(ei);

    k_agg1<<<aggGrid, 256>>>(b1);
    k_gemm<<<gemmGrid, 256>>>(W2);
    k_agg <<<aggGrid, 256>>>(b2);
    k_gemm<<<gemmGrid, 256>>>(W3);
    k_agg <<<aggGrid, 256>>>(b3);

    k_head<<<headGrid, 256>>>(Wp1, bp1, Wp2, bp2, Wt1, bt1, Wt2, bt2, out);
}